// round 12
// baseline (speedup 1.0000x reference)
#include <cuda_runtime.h>

#define N_NODES 100000
#define D_FEAT  128
#define MAX_E   600000
#define GRID    888      // score kernel: one wave at 6 CTAs/SM (148*6)
#define NBC     2368     // convert grid: 16 CTAs/SM for max DRAM MLP
#define TPB     256
#define MAXC    8192
#define QSCALE  16.0f
// int-score margin: 8 score-units * 256 (=16^2). Worst pairwise quant error ~3 units.
#define MARGIN_INT 2048
#define BATCH   6        // edges in flight per warp (12 gathers outstanding)

// Scratch (static __device__ — no allocation allowed). Zero-init on load;
// counters reset by convert_kernel each call (runs first -> replay-safe).
__device__ __align__(128) unsigned g_h8[N_NODES * D_FEAT / 4]; // int8 rows, 128B each
__device__ int      g_score[MAX_E];
__device__ int      g_blockmin[GRID];
__device__ int      g_cand[MAXC];
__device__ float    g_cand_score[MAXC];
__device__ int      g_ncand;
__device__ int      g_bar;     // grid-barrier arrival counter
__device__ int      g_done;    // last-block election

__device__ __forceinline__ unsigned q4(float4 f) {
    int q0 = __float2int_rn(fminf(fmaxf(f.x * QSCALE, -127.f), 127.f));
    int q1 = __float2int_rn(fminf(fmaxf(f.y * QSCALE, -127.f), 127.f));
    int q2 = __float2int_rn(fminf(fmaxf(f.z * QSCALE, -127.f), 127.f));
    int q3 = __float2int_rn(fminf(fmaxf(f.w * QSCALE, -127.f), 127.f));
    return (unsigned)(q0 & 0xFF) | ((unsigned)(q1 & 0xFF) << 8) |
           ((unsigned)(q2 & 0xFF) << 16) | ((unsigned)q3 << 24);
}

// K1: f32 -> int8 quantize h (q = round(16*h), clamp). Resets counters.
__global__ void convert_kernel(const float* __restrict__ h, int n16) {
    if (blockIdx.x == 0 && threadIdx.x == 0) { g_ncand = 0; g_bar = 0; g_done = 0; }
    const float4* __restrict__ h4 = (const float4*)h;
    uint4* __restrict__ o16 = (uint4*)g_h8;
    const int stride = gridDim.x * blockDim.x;
    for (int i = blockIdx.x * blockDim.x + threadIdx.x; i < n16; i += stride) {
        float4 f0 = h4[i * 4 + 0];
        float4 f1 = h4[i * 4 + 1];
        float4 f2 = h4[i * 4 + 2];
        float4 f3 = h4[i * 4 + 3];
        uint4 o;
        o.x = q4(f0); o.y = q4(f1); o.z = q4(f2); o.w = q4(f3);
        o16[i] = o;
    }
}

// K2 (fused score+finalize, persistent single wave, 6 CTAs/SM):
//   Phase A: warp-per-edge dp4a scores; BATCH-edge software pipeline
//            (each lane: 2x LDG.32 per edge -> 12 gathers in flight/warp).
//   Grid barrier (all 888 blocks resident: regs<=40 via launch_bounds).
//   Phase B: gmin, out=1 + candidate select; last block exact rescore.
__global__ void __launch_bounds__(TPB, 6)
score_finalize_kernel(const float* __restrict__ h,
                      const int* __restrict__ src,
                      const int* __restrict__ dst,
                      float* __restrict__ out, int E) {
    __shared__ int   smi[TPB / 32];
    __shared__ float smf[TPB / 32];
    __shared__ bool  s_last;
    const int lane = threadIdx.x & 31;
    const int wid  = threadIdx.x >> 5;
    const int warp = (blockIdx.x * TPB + threadIdx.x) >> 5;
    const int nW   = (GRID * TPB) >> 5;                  // 7104 warps
    const unsigned* __restrict__ h32 = g_h8;             // row = 32 x uint = 128B

    // ---- Phase A: warp-per-edge, BATCH edges pipelined ----
    int lmin = 0x7FFFFFFF;
    {
        int e = warp;
        unsigned s[BATCH], d[BATCH];
        #pragma unroll
        for (int k = 0; k < BATCH; k++) {
            const int ek = e + k * nW;
            const bool v = (ek < E);
            s[k] = v ? (unsigned)src[ek] : 0u;
            d[k] = v ? (unsigned)dst[ek] : 0u;
        }
        while (e < E) {
            // Issue all 2*BATCH gathers (each lane: 4B of the 128B row).
            unsigned a[BATCH], b[BATCH];
            #pragma unroll
            for (int k = 0; k < BATCH; k++) {
                a[k] = h32[s[k] * 32u + (unsigned)lane];
                b[k] = h32[d[k] * 32u + (unsigned)lane];
            }
            // Prefetch next batch indices while gathers are in flight.
            const int en = e + BATCH * nW;
            #pragma unroll
            for (int k = 0; k < BATCH; k++) {
                const int ek = en + k * nW;
                const bool v = (ek < E);
                s[k] = v ? (unsigned)src[ek] : 0u;
                d[k] = v ? (unsigned)dst[ek] : 0u;
            }
            // Consume: 1 dp4a + 1 warp-redux per edge (exact int).
            #pragma unroll
            for (int k = 0; k < BATCH; k++) {
                int c = __dp4a((int)a[k], (int)b[k], 0);
                c = __reduce_add_sync(0xFFFFFFFFu, c);
                const int ek = e + k * nW;
                if (ek < E) {
                    if (lane == 0) g_score[ek] = c;
                    lmin = min(lmin, c);
                }
            }
            e = en;
        }
    }

    lmin = __reduce_min_sync(0xFFFFFFFFu, lmin);
    if (lane == 0) smi[wid] = lmin;
    __syncthreads();
    if (threadIdx.x == 0) {
        int m = smi[0];
        #pragma unroll
        for (int i = 1; i < TPB / 32; i++) m = min(m, smi[i]);
        g_blockmin[blockIdx.x] = m;
    }

    // ---- Grid barrier (safe: one full wave, all blocks resident) ----
    __threadfence();
    __syncthreads();
    if (threadIdx.x == 0) {
        atomicAdd(&g_bar, 1);
        while (*(volatile int*)&g_bar < GRID) __nanosleep(64);
    }
    __syncthreads();

    // ---- Phase B: gmin, out=1, candidate select ----
    int m = 0x7FFFFFFF;
    for (int i = threadIdx.x; i < GRID; i += TPB)
        m = min(m, g_blockmin[i]);
    m = __reduce_min_sync(0xFFFFFFFFu, m);
    if (lane == 0) smi[wid] = m;
    __syncthreads();
    int gmin = smi[0];
    #pragma unroll
    for (int i = 1; i < TPB / 32; i++) gmin = min(gmin, smi[i]);
    const int thresh = gmin + MARGIN_INT;
    __syncthreads();

    const int nth = GRID * TPB;
    for (int e = blockIdx.x * TPB + threadIdx.x; e < E; e += nth) {
        out[e] = 1.0f;
        if (g_score[e] <= thresh) {
            int idx = atomicAdd(&g_ncand, 1);
            if (idx < MAXC) g_cand[idx] = e;
        }
    }

    // ---- Last block: exact fp32 rescore, mark true min ----
    __threadfence();
    if (threadIdx.x == 0) {
        int t = atomicAdd(&g_done, 1);
        s_last = (t == GRID - 1);
    }
    __syncthreads();
    if (!s_last) return;

    const int nc = min(g_ncand, MAXC);
    float wmin = 3.4e38f;
    for (int i = wid; i < nc; i += TPB / 32) {     // warp per candidate
        const int ce = g_cand[i];
        float4 a = ((const float4*)(h + (long long)src[ce] * D_FEAT))[lane];
        float4 b = ((const float4*)(h + (long long)dst[ce] * D_FEAT))[lane];
        float acc = a.x * b.x + a.y * b.y + a.z * b.z + a.w * b.w;
        #pragma unroll
        for (int off = 16; off; off >>= 1)
            acc += __shfl_xor_sync(0xFFFFFFFFu, acc, off);
        if (lane == 0) g_cand_score[i] = acc;
        wmin = fminf(wmin, acc);
    }
    if (lane == 0) smf[wid] = wmin;
    __syncthreads();
    float gm = smf[0];
    #pragma unroll
    for (int i = 1; i < TPB / 32; i++) gm = fminf(gm, smf[i]);

    for (int i = threadIdx.x; i < nc; i += TPB)
        if (g_cand_score[i] == gm) out[g_cand[i]] = 0.0f;
}

extern "C" void kernel_launch(void* const* d_in, const int* in_sizes, int n_in,
                              void* d_out, int out_size) {
    const float* h   = (const float*)d_in[0];
    const int*   src = (const int*)d_in[1];
    const int*   dst = (const int*)d_in[2];
    float* out = (float*)d_out;

    const int E   = in_sizes[1];
    const int n16 = N_NODES * D_FEAT / 16;

    convert_kernel<<<NBC, TPB>>>(h, n16);
    score_finalize_kernel<<<GRID, TPB>>>(h, src, dst, out, E);
}

// round 13
// speedup vs baseline: 1.1187x; 1.1187x over previous
#include <cuda_runtime.h>
#include <cuda_pipeline.h>

#define N_NODES 100000
#define D_FEAT  128
#define MAX_E   600000
#define GRID    888      // score kernel: one wave at 6 CTAs/SM (148*6)
#define NBC     2368     // convert grid
#define TPB     256
#define MAXC    8192
#define QSCALE  16.0f
// int-score margin: 8 score-units * 256 (=16^2). Worst pairwise quant error ~3 units.
#define MARGIN_INT 2048
#define STAGES  4        // smem pipeline depth (3 edges in flight per group)

// Scratch (static __device__ — no allocation allowed). Zero-init on load;
// counters reset by convert_kernel each call (runs first -> replay-safe).
__device__ __align__(128) unsigned g_h8[N_NODES * D_FEAT / 4]; // int8 rows, 128B each
__device__ int      g_score[MAX_E];
__device__ int      g_blockmin[GRID];
__device__ int      g_cand[MAXC];
__device__ float    g_cand_score[MAXC];
__device__ int      g_ncand;
__device__ int      g_bar;     // grid-barrier arrival counter
__device__ int      g_done;    // last-block election

__device__ __forceinline__ unsigned q4(float4 f) {
    int q0 = __float2int_rn(fminf(fmaxf(f.x * QSCALE, -127.f), 127.f));
    int q1 = __float2int_rn(fminf(fmaxf(f.y * QSCALE, -127.f), 127.f));
    int q2 = __float2int_rn(fminf(fmaxf(f.z * QSCALE, -127.f), 127.f));
    int q3 = __float2int_rn(fminf(fmaxf(f.w * QSCALE, -127.f), 127.f));
    return (unsigned)(q0 & 0xFF) | ((unsigned)(q1 & 0xFF) << 8) |
           ((unsigned)(q2 & 0xFF) << 16) | ((unsigned)q3 << 24);
}

__device__ __forceinline__ int dot_i8_16B(uint4 ua, uint4 ub) {
    int acc = __dp4a((int)ua.x, (int)ub.x, 0);
    acc = __dp4a((int)ua.y, (int)ub.y, acc);
    acc = __dp4a((int)ua.z, (int)ub.z, acc);
    acc = __dp4a((int)ua.w, (int)ub.w, acc);
    return acc;
}

// K1: f32 -> int8 quantize h (q = round(16*h), clamp). Resets counters.
__global__ void convert_kernel(const float* __restrict__ h, int n16) {
    if (blockIdx.x == 0 && threadIdx.x == 0) { g_ncand = 0; g_bar = 0; g_done = 0; }
    const float4* __restrict__ h4 = (const float4*)h;
    uint4* __restrict__ o16 = (uint4*)g_h8;
    const int stride = gridDim.x * blockDim.x;
    for (int i = blockIdx.x * blockDim.x + threadIdx.x; i < n16; i += stride) {
        float4 f0 = h4[i * 4 + 0];
        float4 f1 = h4[i * 4 + 1];
        float4 f2 = h4[i * 4 + 2];
        float4 f3 = h4[i * 4 + 3];
        uint4 o;
        o.x = q4(f0); o.y = q4(f1); o.z = q4(f2); o.w = q4(f3);
        o16[i] = o;
    }
}

// K2 (fused score+finalize, persistent single wave, 6 CTAs/SM):
//   Phase A: 8-lane group per edge; rows staged via cp.async into a 4-deep
//            smem ring (3 edges / 6 row-gathers in flight per group, zero
//            register cost), consumed with LDS.128 + dp4a + 8-lane redux.
//   Grid barrier (one full wave resident).
//   Phase B: gmin + candidate select; last block exact fp32 rescore.
__global__ void __launch_bounds__(TPB, 6)
score_finalize_kernel(const float* __restrict__ h,
                      const int* __restrict__ src,
                      const int* __restrict__ dst,
                      float* __restrict__ out, int E) {
    // [warp][stage][group][row][lane8] = 8*4*4*2*8 * 16B = 32 KB
    __shared__ __align__(16) uint4 sbuf[TPB / 32][STAGES][4][2][8];
    __shared__ int   smi[TPB / 32];
    __shared__ float smf[TPB / 32];
    __shared__ bool  s_last;
    const int lane = threadIdx.x & 31;
    const int wid  = threadIdx.x >> 5;
    const int grp  = lane >> 3;            // group within warp
    const unsigned gl    = lane & 7;       // lane within group
    const unsigned gmask = 0xFFu << (lane & 24);
    const int gid  = (blockIdx.x * TPB + threadIdx.x) >> 3;   // global group id
    const int nG   = (GRID * TPB) >> 3;                       // 28416 groups
    const uint4* __restrict__ h8 = (const uint4*)g_h8;        // row = 8 x uint4

    // ---- Phase A: cp.async staged pipeline ----
    int lmin = 0x7FFFFFFF;
    {
        // Prologue: issue stages for edges j=0..STAGES-2.
        #pragma unroll
        for (int p = 0; p < STAGES - 1; p++) {
            const int ep = gid + p * nG;
            if (ep < E) {
                const unsigned s = (unsigned)src[ep];
                const unsigned d = (unsigned)dst[ep];
                __pipeline_memcpy_async(&sbuf[wid][p][grp][0][gl],
                                        &h8[s * 8u + gl], 16);
                __pipeline_memcpy_async(&sbuf[wid][p][grp][1][gl],
                                        &h8[d * 8u + gl], 16);
            }
            __pipeline_commit();
        }
        for (int j = 0; ; j++) {
            const int e = gid + j * nG;
            if (e >= E) break;
            // Issue stage j+STAGES-1 (keep 3 edges in flight).
            const int ep = gid + (j + STAGES - 1) * nG;
            if (ep < E) {
                const unsigned s = (unsigned)src[ep];
                const unsigned d = (unsigned)dst[ep];
                const int st = (j + STAGES - 1) & (STAGES - 1);
                __pipeline_memcpy_async(&sbuf[wid][st][grp][0][gl],
                                        &h8[s * 8u + gl], 16);
                __pipeline_memcpy_async(&sbuf[wid][st][grp][1][gl],
                                        &h8[d * 8u + gl], 16);
            }
            __pipeline_commit();
            // Wait until stage j's group has landed (<= STAGES-1 outstanding).
            __pipeline_wait_prior(STAGES - 1);

            const int st = j & (STAGES - 1);
            uint4 ua = sbuf[wid][st][grp][0][gl];
            uint4 ub = sbuf[wid][st][grp][1][gl];
            int c = dot_i8_16B(ua, ub);
            c = __reduce_add_sync(gmask, c);
            if (gl == 0) { g_score[e] = c; out[e] = 1.0f; }
            lmin = min(lmin, c);
        }
        __pipeline_wait_prior(0);
    }

    lmin = __reduce_min_sync(0xFFFFFFFFu, lmin);
    if (lane == 0) smi[wid] = lmin;
    __syncthreads();
    if (threadIdx.x == 0) {
        int m = smi[0];
        #pragma unroll
        for (int i = 1; i < TPB / 32; i++) m = min(m, smi[i]);
        g_blockmin[blockIdx.x] = m;
    }

    // ---- Grid barrier (safe: one full wave, all blocks resident) ----
    __threadfence();
    __syncthreads();
    if (threadIdx.x == 0) {
        atomicAdd(&g_bar, 1);
        while (*(volatile int*)&g_bar < GRID) __nanosleep(64);
    }
    __syncthreads();

    // ---- Phase B: gmin, candidate select (out=1 already written in A) ----
    int m = 0x7FFFFFFF;
    for (int i = threadIdx.x; i < GRID; i += TPB)
        m = min(m, g_blockmin[i]);
    m = __reduce_min_sync(0xFFFFFFFFu, m);
    if (lane == 0) smi[wid] = m;
    __syncthreads();
    int gmin = smi[0];
    #pragma unroll
    for (int i = 1; i < TPB / 32; i++) gmin = min(gmin, smi[i]);
    const int thresh = gmin + MARGIN_INT;
    __syncthreads();

    const int nth = GRID * TPB;
    for (int e = blockIdx.x * TPB + threadIdx.x; e < E; e += nth) {
        if (g_score[e] <= thresh) {
            int idx = atomicAdd(&g_ncand, 1);
            if (idx < MAXC) g_cand[idx] = e;
        }
    }

    // ---- Last block: exact fp32 rescore, mark true min ----
    __threadfence();
    if (threadIdx.x == 0) {
        int t = atomicAdd(&g_done, 1);
        s_last = (t == GRID - 1);
    }
    __syncthreads();
    if (!s_last) return;

    const int nc = min(g_ncand, MAXC);
    float wmin = 3.4e38f;
    for (int i = wid; i < nc; i += TPB / 32) {     // warp per candidate
        const int ce = g_cand[i];
        float4 a = ((const float4*)(h + (long long)src[ce] * D_FEAT))[lane];
        float4 b = ((const float4*)(h + (long long)dst[ce] * D_FEAT))[lane];
        float acc = a.x * b.x + a.y * b.y + a.z * b.z + a.w * b.w;
        #pragma unroll
        for (int off = 16; off; off >>= 1)
            acc += __shfl_xor_sync(0xFFFFFFFFu, acc, off);
        if (lane == 0) g_cand_score[i] = acc;
        wmin = fminf(wmin, acc);
    }
    if (lane == 0) smf[wid] = wmin;
    __syncthreads();
    float gm = smf[0];
    #pragma unroll
    for (int i = 1; i < TPB / 32; i++) gm = fminf(gm, smf[i]);

    for (int i = threadIdx.x; i < nc; i += TPB)
        if (g_cand_score[i] == gm) out[g_cand[i]] = 0.0f;
}

extern "C" void kernel_launch(void* const* d_in, const int* in_sizes, int n_in,
                              void* d_out, int out_size) {
    const float* h   = (const float*)d_in[0];
    const int*   src = (const int*)d_in[1];
    const int*   dst = (const int*)d_in[2];
    float* out = (float*)d_out;

    const int E   = in_sizes[1];
    const int n16 = N_NODES * D_FEAT / 16;

    convert_kernel<<<NBC, TPB>>>(h, n16);
    score_finalize_kernel<<<GRID, TPB>>>(h, src, dst, out, E);
}

// round 14
// speedup vs baseline: 1.1644x; 1.0409x over previous
#include <cuda_runtime.h>

#define N_NODES 100000
#define D_FEAT  128
#define MAX_E   600000
#define GRID    888      // score kernel: one wave at 6 CTAs/SM (148*6)
#define NBC     2368     // convert grid
#define TPB     256
#define MAXC    24576
// raw units = 256 * (1.6)^2 * score ~ 655*score. 18500 raw ~ 28 score units,
// >> 2x max int4 quant error (~2x13.5). Expected candidates ~10k.
#define MARGIN_RAW 18500

// Scratch (static __device__ — no allocation allowed). Zero-init on load;
// counters reset by convert_kernel each call (runs first -> replay-safe).
__device__ __align__(128) unsigned g_h4[N_NODES * D_FEAT / 8]; // nibble rows, 64B each
__device__ int      g_score[MAX_E];          // coarse raw int scores
__device__ int      g_blockmin[GRID];
__device__ int      g_cand[MAXC];
__device__ unsigned g_cand_enc[MAXC];        // encoded exact scores
__device__ int      g_ncand;
__device__ unsigned g_emin_enc;              // encoded exact min over candidates
__device__ int      g_bar;                   // monotonic grid-barrier counter
__device__ int      g_done;                  // last-block election

// Monotone float->uint encoding: a < b  <=>  enc(a) < enc(b).
__device__ __forceinline__ unsigned enc_f32(float f) {
    unsigned b = __float_as_uint(f);
    return (b & 0x80000000u) ? ~b : (b | 0x80000000u);
}

__device__ __forceinline__ unsigned pack8(float4 a, float4 b) {
    const float S = 1.6f;
    float v[8] = {a.x, a.y, a.z, a.w, b.x, b.y, b.z, b.w};
    unsigned r = 0;
    #pragma unroll
    for (int i = 0; i < 8; i++) {
        int q = __float2int_rn(fminf(fmaxf(v[i] * S, -8.f), 7.f));
        r |= ((unsigned)(q & 0xF)) << (4 * i);
    }
    return r;
}

// Signed-nibble dot of 16 elements (one uint2 per side) via high-nibble trick:
// byte = q*16 (signed), dp4a pair-sum = 256 * sum(q_a * q_b). Exact integer.
__device__ __forceinline__ int dot_nib(uint2 a, uint2 b) {
    int c;
    c = __dp4a((int)(a.x & 0xF0F0F0F0u),        (int)(b.x & 0xF0F0F0F0u),        0);
    c = __dp4a((int)((a.x << 4) & 0xF0F0F0F0u), (int)((b.x << 4) & 0xF0F0F0F0u), c);
    c = __dp4a((int)(a.y & 0xF0F0F0F0u),        (int)(b.y & 0xF0F0F0F0u),        c);
    c = __dp4a((int)((a.y << 4) & 0xF0F0F0F0u), (int)((b.y << 4) & 0xF0F0F0F0u), c);
    return c;
}

// K1: f32 -> packed int4 rows (64B/node). Resets counters (runs first).
__global__ void convert_kernel(const float* __restrict__ h, int n8) {
    if (blockIdx.x == 0 && threadIdx.x == 0) {
        g_ncand = 0; g_bar = 0; g_done = 0; g_emin_enc = 0xFFFFFFFFu;
    }
    const float4* __restrict__ h4 = (const float4*)h;
    const int stride = gridDim.x * blockDim.x;
    for (int i = blockIdx.x * blockDim.x + threadIdx.x; i < n8; i += stride) {
        float4 a = h4[i * 2 + 0];
        float4 b = h4[i * 2 + 1];
        g_h4[i] = pack8(a, b);
    }
}

// K2 (fused, persistent single wave, 6 CTAs/SM):
//   Phase A: coarse int4 scores; 8-lane group/edge, uint2 (8B) per lane,
//            2-edge prefetch pipeline (R11 structure, half the bytes).
//   Barrier. Phase B: gmin, out=1, candidate select (<= ~10k expected).
//   Barrier. Phase C: grid-parallel exact fp32 rescore + atomicMin.
//   Last-block election: mark true-min edge(s).
__global__ void __launch_bounds__(TPB, 6)
score_finalize_kernel(const float* __restrict__ h,
                      const int* __restrict__ src,
                      const int* __restrict__ dst,
                      float* __restrict__ out, int E) {
    __shared__ int  smi[TPB / 32];
    __shared__ bool s_last;
    const int lane = threadIdx.x & 31;
    const int wid  = threadIdx.x >> 5;
    const unsigned gl    = lane & 7;
    const unsigned gmask = 0xFFu << (lane & 24);
    const int gid  = (blockIdx.x * TPB + threadIdx.x) >> 3;
    const int nG   = (GRID * TPB) >> 3;
    const uint2* __restrict__ h2 = (const uint2*)g_h4;   // row = 8 x uint2 = 64B

    // ---- Phase A: 2 edges in flight + next-iteration index prefetch ----
    int lmin = 0x7FFFFFFF;
    {
        int e = gid;
        const bool v1i = (e + nG < E);
        unsigned s0 = (e < E) ? (unsigned)src[e] : 0u;
        unsigned d0 = (e < E) ? (unsigned)dst[e] : 0u;
        unsigned s1 = v1i ? (unsigned)src[e + nG] : 0u;
        unsigned d1 = v1i ? (unsigned)dst[e + nG] : 0u;

        while (e < E) {
            uint2 ua0 = h2[s0 * 8u + gl];
            uint2 ub0 = h2[d0 * 8u + gl];
            uint2 ua1 = h2[s1 * 8u + gl];
            uint2 ub1 = h2[d1 * 8u + gl];

            const int en = e + 2 * nG;
            const bool vn0 = (en < E);
            const bool vn1 = (en + nG < E);
            s0 = vn0 ? (unsigned)src[en] : 0u;
            d0 = vn0 ? (unsigned)dst[en] : 0u;
            s1 = vn1 ? (unsigned)src[en + nG] : 0u;
            d1 = vn1 ? (unsigned)dst[en + nG] : 0u;

            int c0 = dot_nib(ua0, ub0);
            int c1 = dot_nib(ua1, ub1);
            c0 = __reduce_add_sync(gmask, c0);
            c1 = __reduce_add_sync(gmask, c1);

            if (gl == 0) g_score[e] = c0;
            lmin = min(lmin, c0);
            if (e + nG < E) {
                if (gl == 0) g_score[e + nG] = c1;
                lmin = min(lmin, c1);
            }
            e = en;
        }
    }

    lmin = __reduce_min_sync(0xFFFFFFFFu, lmin);
    if (lane == 0) smi[wid] = lmin;
    __syncthreads();
    if (threadIdx.x == 0) {
        int m = smi[0];
        #pragma unroll
        for (int i = 1; i < TPB / 32; i++) m = min(m, smi[i]);
        g_blockmin[blockIdx.x] = m;
    }

    // ---- Grid barrier #1 ----
    __threadfence();
    __syncthreads();
    if (threadIdx.x == 0) {
        atomicAdd(&g_bar, 1);
        while (*(volatile int*)&g_bar < GRID) __nanosleep(64);
    }
    __syncthreads();

    // ---- Phase B: gmin, out=1, candidate select ----
    int m = 0x7FFFFFFF;
    for (int i = threadIdx.x; i < GRID; i += TPB)
        m = min(m, g_blockmin[i]);
    m = __reduce_min_sync(0xFFFFFFFFu, m);
    if (lane == 0) smi[wid] = m;
    __syncthreads();
    int gmin = smi[0];
    #pragma unroll
    for (int i = 1; i < TPB / 32; i++) gmin = min(gmin, smi[i]);
    const int thresh = gmin + MARGIN_RAW;
    __syncthreads();

    const int nth = GRID * TPB;
    for (int e = blockIdx.x * TPB + threadIdx.x; e < E; e += nth) {
        out[e] = 1.0f;
        if (g_score[e] <= thresh) {
            int idx = atomicAdd(&g_ncand, 1);
            if (idx < MAXC) g_cand[idx] = e;
        }
    }

    // ---- Grid barrier #2 (candidate list complete) ----
    __threadfence();
    __syncthreads();
    if (threadIdx.x == 0) {
        atomicAdd(&g_bar, 1);
        while (*(volatile int*)&g_bar < 2 * GRID) __nanosleep(64);
    }
    __syncthreads();

    // ---- Phase C: grid-parallel exact fp32 rescore, global encoded min ----
    const int nc = min(*(volatile int*)&g_ncand, MAXC);
    {
        const int warp = (blockIdx.x * TPB + threadIdx.x) >> 5;
        const int nW   = (GRID * TPB) >> 5;
        for (int i = warp; i < nc; i += nW) {
            const int ce = g_cand[i];
            float4 a = ((const float4*)(h + (long long)src[ce] * D_FEAT))[lane];
            float4 b = ((const float4*)(h + (long long)dst[ce] * D_FEAT))[lane];
            float acc = a.x * b.x + a.y * b.y + a.z * b.z + a.w * b.w;
            #pragma unroll
            for (int off = 16; off; off >>= 1)
                acc += __shfl_xor_sync(0xFFFFFFFFu, acc, off);
            if (lane == 0) {
                unsigned en = enc_f32(acc);
                g_cand_enc[i] = en;
                atomicMin(&g_emin_enc, en);
            }
        }
    }

    // ---- Last-block election: mark exact-min edge(s) ----
    __threadfence();
    if (threadIdx.x == 0) {
        int t = atomicAdd(&g_done, 1);
        s_last = (t == GRID - 1);
    }
    __syncthreads();
    if (!s_last) return;

    const unsigned gm = *(volatile unsigned*)&g_emin_enc;
    for (int i = threadIdx.x; i < nc; i += TPB)
        if (g_cand_enc[i] == gm) out[g_cand[i]] = 0.0f;
}

extern "C" void kernel_launch(void* const* d_in, const int* in_sizes, int n_in,
                              void* d_out, int out_size) {
    const float* h   = (const float*)d_in[0];
    const int*   src = (const int*)d_in[1];
    const int*   dst = (const int*)d_in[2];
    float* out = (float*)d_out;

    const int E  = in_sizes[1];
    const int n8 = N_NODES * D_FEAT / 8;   // packed uints

    convert_kernel<<<NBC, TPB>>>(h, n8);
    score_finalize_kernel<<<GRID, TPB>>>(h, src, dst, out, E);
}

// round 15
// speedup vs baseline: 1.2393x; 1.0644x over previous
#include <cuda_runtime.h>

#define N_NODES 100000
#define D_FEAT  128
#define MAX_E   600000
#define GRID    888      // score kernel: one wave at 6 CTAs/SM (148*6)
#define NBC     2368     // convert grid
#define TPB     256
#define MAXC    8192
#define QSCALE  16.0f
// int-score margin: 8 score-units * 256 (=16^2). Worst pairwise quant error ~3 units.
#define MARGIN_INT 2048

// Scratch (static __device__ — no allocation allowed). Zero-init on load;
// counters reset by convert_kernel each call (runs first -> replay-safe).
__device__ __align__(128) unsigned g_h8[N_NODES * D_FEAT / 4]; // int8 rows, 128B each
__device__ int      g_score[MAX_E];
__device__ int      g_blockmin[GRID];
__device__ int      g_cand[MAXC];
__device__ float    g_cand_score[MAXC];
__device__ int      g_ncand;
__device__ int      g_bar;     // grid-barrier arrival counter
__device__ int      g_done;    // last-block election

__device__ __forceinline__ unsigned q4(float4 f) {
    int q0 = __float2int_rn(fminf(fmaxf(f.x * QSCALE, -127.f), 127.f));
    int q1 = __float2int_rn(fminf(fmaxf(f.y * QSCALE, -127.f), 127.f));
    int q2 = __float2int_rn(fminf(fmaxf(f.z * QSCALE, -127.f), 127.f));
    int q3 = __float2int_rn(fminf(fmaxf(f.w * QSCALE, -127.f), 127.f));
    return (unsigned)(q0 & 0xFF) | ((unsigned)(q1 & 0xFF) << 8) |
           ((unsigned)(q2 & 0xFF) << 16) | ((unsigned)q3 << 24);
}

__device__ __forceinline__ int dot_i8_16B(uint4 ua, uint4 ub) {
    int acc = __dp4a((int)ua.x, (int)ub.x, 0);
    acc = __dp4a((int)ua.y, (int)ub.y, acc);
    acc = __dp4a((int)ua.z, (int)ub.z, acc);
    acc = __dp4a((int)ua.w, (int)ub.w, acc);
    return acc;
}

// K1: f32 -> int8 quantize h (q = round(16*h), clamp). Resets counters.
__global__ void convert_kernel(const float* __restrict__ h, int n16) {
    if (blockIdx.x == 0 && threadIdx.x == 0) { g_ncand = 0; g_bar = 0; g_done = 0; }
    const float4* __restrict__ h4 = (const float4*)h;
    uint4* __restrict__ o16 = (uint4*)g_h8;
    const int stride = gridDim.x * blockDim.x;
    for (int i = blockIdx.x * blockDim.x + threadIdx.x; i < n16; i += stride) {
        float4 f0 = h4[i * 4 + 0];
        float4 f1 = h4[i * 4 + 1];
        float4 f2 = h4[i * 4 + 2];
        float4 f3 = h4[i * 4 + 3];
        uint4 o;
        o.x = q4(f0); o.y = q4(f1); o.z = q4(f2); o.w = q4(f3);
        o16[i] = o;
    }
}

// K2 (fused score+finalize, persistent single wave, 6 CTAs/SM):
//   Phase A: warp owns a CONTIGUOUS 85-edge span. Group g handles edges
//            base+2g, base+2g+1 (stride 8/iter) -> index loads land in one
//            16B window and score stores in one 32B window per warp LDG/STG
//            (1 wavefront instead of 4). Gathers unchanged (random rows).
//   Grid barrier (one full wave resident).
//   Phase B: gmin, out=1 + candidate select; last block exact rescore.
__global__ void __launch_bounds__(TPB, 6)
score_finalize_kernel(const float* __restrict__ h,
                      const int* __restrict__ src,
                      const int* __restrict__ dst,
                      float* __restrict__ out, int E) {
    __shared__ int   smi[TPB / 32];
    __shared__ float smf[TPB / 32];
    __shared__ bool  s_last;
    const int lane = threadIdx.x & 31;
    const int wid  = threadIdx.x >> 5;
    const int grp  = lane >> 3;
    const unsigned gl    = lane & 7;
    const unsigned gmask = 0xFFu << (lane & 24);
    const uint4* __restrict__ h8 = (const uint4*)g_h8;   // row = 8 x uint4 = 128B

    // ---- Phase A: contiguous spans, 2 edges in flight + index prefetch ----
    int lmin = 0x7FFFFFFF;
    {
        const int warp = (blockIdx.x * TPB + threadIdx.x) >> 5;
        const int nW   = (GRID * TPB) >> 5;              // 7104 warps
        const int span = (E + nW - 1) / nW;              // 85
        const int eend = min(warp * span + span, E);
        int e = warp * span + grp * 2;                   // this group's first edge

        bool v0 = (e < eend), v1 = (e + 1 < eend);
        unsigned s0 = v0 ? (unsigned)src[e] : 0u;
        unsigned d0 = v0 ? (unsigned)dst[e] : 0u;
        unsigned s1 = v1 ? (unsigned)src[e + 1] : 0u;
        unsigned d1 = v1 ? (unsigned)dst[e + 1] : 0u;

        while (e < eend) {
            // Issue all 4 gathers first (MLP 4 per group, 16/warp).
            uint4 ua0 = h8[s0 * 8u + gl];
            uint4 ub0 = h8[d0 * 8u + gl];
            uint4 ua1 = h8[s1 * 8u + gl];
            uint4 ub1 = h8[d1 * 8u + gl];

            // Prefetch next pair's indices (16B window per warp -> 1 wf).
            const int en = e + 8;
            const bool vn0 = (en < eend);
            const bool vn1 = (en + 1 < eend);
            s0 = vn0 ? (unsigned)src[en] : 0u;
            d0 = vn0 ? (unsigned)dst[en] : 0u;
            s1 = vn1 ? (unsigned)src[en + 1] : 0u;
            d1 = vn1 ? (unsigned)dst[en + 1] : 0u;

            // Consume.
            int c0 = dot_i8_16B(ua0, ub0);
            int c1 = dot_i8_16B(ua1, ub1);
            c0 = __reduce_add_sync(gmask, c0);
            c1 = __reduce_add_sync(gmask, c1);

            if (gl == 0) g_score[e] = c0;        // 32B window per warp
            lmin = min(lmin, c0);
            if (e + 1 < eend) {
                if (gl == 0) g_score[e + 1] = c1;
                lmin = min(lmin, c1);
            }
            e = en;
        }
    }

    lmin = __reduce_min_sync(0xFFFFFFFFu, lmin);
    if (lane == 0) smi[wid] = lmin;
    __syncthreads();
    if (threadIdx.x == 0) {
        int m = smi[0];
        #pragma unroll
        for (int i = 1; i < TPB / 32; i++) m = min(m, smi[i]);
        g_blockmin[blockIdx.x] = m;
    }

    // ---- Grid barrier (safe: one full wave, all blocks resident) ----
    __threadfence();
    __syncthreads();
    if (threadIdx.x == 0) {
        atomicAdd(&g_bar, 1);
        while (*(volatile int*)&g_bar < GRID) __nanosleep(64);
    }
    __syncthreads();

    // ---- Phase B: gmin, out=1, candidate select ----
    int m = 0x7FFFFFFF;
    for (int i = threadIdx.x; i < GRID; i += TPB)
        m = min(m, g_blockmin[i]);
    m = __reduce_min_sync(0xFFFFFFFFu, m);
    if (lane == 0) smi[wid] = m;
    __syncthreads();
    int gmin = smi[0];
    #pragma unroll
    for (int i = 1; i < TPB / 32; i++) gmin = min(gmin, smi[i]);
    const int thresh = gmin + MARGIN_INT;
    __syncthreads();

    const int nth = GRID * TPB;
    for (int e = blockIdx.x * TPB + threadIdx.x; e < E; e += nth) {
        out[e] = 1.0f;
        if (g_score[e] <= thresh) {
            int idx = atomicAdd(&g_ncand, 1);
            if (idx < MAXC) g_cand[idx] = e;
        }
    }

    // ---- Last block: exact fp32 rescore, mark true min ----
    __threadfence();
    if (threadIdx.x == 0) {
        int t = atomicAdd(&g_done, 1);
        s_last = (t == GRID - 1);
    }
    __syncthreads();
    if (!s_last) return;

    const int nc = min(g_ncand, MAXC);
    float wmin = 3.4e38f;
    for (int i = wid; i < nc; i += TPB / 32) {     // warp per candidate
        const int ce = g_cand[i];
        float4 a = ((const float4*)(h + (long long)src[ce] * D_FEAT))[lane];
        float4 b = ((const float4*)(h + (long long)dst[ce] * D_FEAT))[lane];
        float acc = a.x * b.x + a.y * b.y + a.z * b.z + a.w * b.w;
        #pragma unroll
        for (int off = 16; off; off >>= 1)
            acc += __shfl_xor_sync(0xFFFFFFFFu, acc, off);
        if (lane == 0) g_cand_score[i] = acc;
        wmin = fminf(wmin, acc);
    }
    if (lane == 0) smf[wid] = wmin;
    __syncthreads();
    float gm = smf[0];
    #pragma unroll
    for (int i = 1; i < TPB / 32; i++) gm = fminf(gm, smf[i]);

    for (int i = threadIdx.x; i < nc; i += TPB)
        if (g_cand_score[i] == gm) out[g_cand[i]] = 0.0f;
}

extern "C" void kernel_launch(void* const* d_in, const int* in_sizes, int n_in,
                              void* d_out, int out_size) {
    const float* h   = (const float*)d_in[0];
    const int*   src = (const int*)d_in[1];
    const int*   dst = (const int*)d_in[2];
    float* out = (float*)d_out;

    const int E   = in_sizes[1];
    const int n16 = N_NODES * D_FEAT / 16;

    convert_kernel<<<NBC, TPB>>>(h, n16);
    score_finalize_kernel<<<GRID, TPB>>>(h, src, dst, out, E);
}